// round 17
// baseline (speedup 1.0000x reference)
#include <cuda_runtime.h>

#define NHID 25
#define NSTEP 20
#define DTV (1.0/60.0)
#define DTF 0.016666666666666666f
#define EPSV 1e-4f
#define PQV 5.0f
#define QVV 200.0f
#define QAV 1.0f

// Precomputed constants: q0af[25] | c1[20] | c2[20]
__device__ float g_consts[NHID + 2 * NSTEP];
__device__ unsigned g_flag;   // zero-initialized at module load
__device__ unsigned g_done;   // completion counter for per-launch reset

// ---------------------------------------------------------------------------
// SINGLE fused kernel. R16 post-mortem: setup+overhead still ~12us with a
// 2-kernel PDL chain (second graph node + end-of-kernel completion wait).
// Here block 0 / warp 0 computes the constants inline (identical math to the
// benched R16 setup, rel_err 6.9e-7), publishes via fence+flag; all other
// warps spin AFTER issuing their phase-1 x loads. Last block resets the
// flag/counter -> deterministic across graph replays. No block waits on a
// later block -> no deadlock even if not all blocks were resident.
// ---------------------------------------------------------------------------
__global__ void __launch_bounds__(128, 8) fused_kernel(const float* __restrict__ x,
                                                       const float* __restrict__ gp,
                                                       const float* __restrict__ gv,
                                                       const float* __restrict__ Af,
                                                       const float* __restrict__ Lq,
                                                       float* __restrict__ out) {
    __shared__ float sx[128 * NHID];          // 12.8 KB; warp w owns [w*800, w*800+800)
    __shared__ float strip[3 * 128];          // dp | p | v per row
    __shared__ float scw[4][80];              // per-warp consts
    __shared__ double sqrow[NSTEP][NSTEP + 1];// fp64 Qf rows (block 0 only; pad 21)
    const int t = threadIdx.x;
    const int w = t >> 5;
    const int lane = t & 31;
    const int base = blockIdx.x * 128;
    const unsigned FULL = 0xffffffffu;

    // ---- Phase 1 (independent of constants): warp-local float4 stage of x.
    const float4* xb4 = (const float4*)(x + (size_t)base * NHID);
    float4* sx4 = (float4*)sx;
#pragma unroll
    for (int k = 0; k < 7; k++) {
        int i = k * 32 + lane;
        if (i < 200) {
            int idx = w * 200 + i;
            sx4[idx] = xb4[idx];
        }
    }
    const float p = gp[base + t];
    const float v = gv[base + t];

    // ---- Block 0 / warp 0: compute the 65 constants (R16-verified math) ----
    if (blockIdx.x == 0 && w == 0) {
        const float dtf = DTF, dt2f = DTF * DTF;
        const bool lh = (lane < NHID);
        const bool ls = (lane < NSTEP);

        float af = lh ? Af[lane] : 0.0f;

        float g0 = 0.0f, g1 = 0.0f;
#pragma unroll
        for (int j = 0; j < NHID - 1; j += 2) {
            float aj0 = __shfl_sync(FULL, af, j);
            float aj1 = __shfl_sync(FULL, af, j + 1);
            float l0 = lh ? Lq[j * NHID + lane] : 0.0f;
            float l1 = lh ? Lq[(j + 1) * NHID + lane] : 0.0f;
            g0 = fmaf(l0, aj0, g0);
            g1 = fmaf(l1, aj1, g1);
        }
        {
            float aj = __shfl_sync(FULL, af, NHID - 1);
            float l = lh ? Lq[(NHID - 1) * NHID + lane] : 0.0f;
            g0 = fmaf(l, aj, g0);
        }
        float gg = g0 + g1;

        float q0a = 0.0f, q0b = 0.0f;
#pragma unroll
        for (int i = 0; i < NHID - 1; i += 2) {
            float gi0 = __shfl_sync(FULL, gg, i);
            float gi1 = __shfl_sync(FULL, gg, i + 1);
            float l0 = lh ? Lq[lane * NHID + i] : 0.0f;
            float l1 = lh ? Lq[lane * NHID + i + 1] : 0.0f;
            q0a = fmaf(l0, gi0, q0a);
            q0b = fmaf(l1, gi1, q0b);
        }
        {
            float gi = __shfl_sync(FULL, gg, NHID - 1);
            float l = lh ? Lq[lane * NHID + NHID - 1] : 0.0f;
            q0a = fmaf(l, gi, q0a);
        }
        float q0 = fmaf(EPSV, af, q0a + q0b);

        float acc = fmaf(gg, gg, EPSV * af * af);
#pragma unroll
        for (int o = 16; o > 0; o >>= 1) acc += __shfl_xor_sync(FULL, acc, o);
        const float alpha = acc;

        // suffix sums (integer-exact in fp32)
        float s0 = 0, s1 = 0, s2 = 0;
        if (ls) {
            for (int r = lane; r < NSTEP; r++) {
                float ww = (r == NSTEP - 1) ? PQV : 1.0f;
                s0 += ww; s1 += ww * r; s2 += ww * (float)(r * r);
            }
        }

        float v1 = 0, p26 = 0;
        if (ls) {
            float c = (float)lane;
            v1  = 2.0f * dtf * (s1 - c * s0);
            p26 = 2.0f * dtf * (alpha * (s2 + (1.0f - c) * s1 - c * s0) + QVV * s0);
        }

        // Qf row: fp64 cache in smem + fp32 working copy in regs
        float rr[NSTEP];
        {
            const double dt2d = DTV * DTV;
            const double sA = 2.0 * dt2d * (double)alpha;
            const double sB = 2.0 * (double)QVV * dt2d;
#pragma unroll
            for (int j = 0; j < NSTEP; j++) {
                float sj0 = __shfl_sync(FULL, s0, j);
                float sj1 = __shfl_sync(FULL, s1, j);
                float sj2 = __shfl_sync(FULL, s2, j);
                float m0 = (j > lane) ? sj0 : s0;
                float m1 = (j > lane) ? sj1 : s1;
                float m2 = (j > lane) ? sj2 : s2;
                float C = m2 - (float)(lane + j) * m1 + (float)(lane * j) * m0; // exact
                double q = sA * (double)C + sB * (double)m0;
                if (j == lane) q += 2.0 * (double)QAV + (double)EPSV;
                if (ls) sqrow[lane][j] = q;
                rr[j] = ls ? (float)q : 0.0f;
            }
        }

        // In-place compact Gauss-Jordan (SPD, no pivoting)
#pragma unroll
        for (int k = 0; k < NSTEP; k++) {
            float pk = __shfl_sync(FULL, rr[k], k);
            float d = 1.0f / pk;
            float tt = rr[k];
            bool isp = (lane == k);
#pragma unroll
            for (int j = 0; j < NSTEP; j++) {
                float pj = __shfl_sync(FULL, rr[j], k);
                float pjd = pj * d;
                rr[j] = isp ? pjd : fmaf(-tt, pjd, rr[j]);
            }
            rr[k] = isp ? d : -tt * d;
        }

        // y = inv * rhs (fp32, split chains)
        float ya0 = 0, ya1 = 0, yb0 = 0, yb1 = 0;
#pragma unroll
        for (int j = 0; j < NSTEP; j += 2) {
            float vj0 = __shfl_sync(FULL, v1, j);
            float vj1 = __shfl_sync(FULL, v1, j + 1);
            float pj0 = __shfl_sync(FULL, p26, j);
            float pj1 = __shfl_sync(FULL, p26, j + 1);
            ya0 = fmaf(rr[j], vj0, ya0);
            ya1 = fmaf(rr[j + 1], vj1, ya1);
            yb0 = fmaf(rr[j], pj0, yb0);
            yb1 = fmaf(rr[j + 1], pj1, yb1);
        }
        double y1 = (double)(ya0 + ya1), y2 = (double)(yb0 + yb1);

        // ONE fp64 refinement round, split accumulators (qrow from smem)
        {
            double a0 = 0, a1 = 0, c0 = 0, c1 = 0;
#pragma unroll
            for (int j = 0; j < NSTEP; j += 2) {
                double u0 = __shfl_sync(FULL, y1, j);
                double u1 = __shfl_sync(FULL, y1, j + 1);
                double w0 = __shfl_sync(FULL, y2, j);
                double w1 = __shfl_sync(FULL, y2, j + 1);
                double qa = ls ? sqrow[lane][j] : 0.0;
                double qb = ls ? sqrow[lane][j + 1] : 0.0;
                a0 += qa * u0; a1 += qb * u1;
                c0 += qa * w0; c1 += qb * w1;
            }
            double res1 = (double)v1 - (a0 + a1);
            double res2 = (double)p26 - (c0 + c1);
            double d0 = 0, d1 = 0, e0 = 0, e1 = 0;
#pragma unroll
            for (int j = 0; j < NSTEP; j += 2) {
                double r0 = __shfl_sync(FULL, res1, j);
                double r1 = __shfl_sync(FULL, res1, j + 1);
                double t0 = __shfl_sync(FULL, res2, j);
                double t1 = __shfl_sync(FULL, res2, j + 1);
                d0 += (double)rr[j] * r0;
                d1 += (double)rr[j + 1] * r1;
                e0 += (double)rr[j] * t0;
                e1 += (double)rr[j + 1] * t1;
            }
            y1 += d0 + d1;
            y2 += e0 + e1;
        }

        // epilogue (fp32 triangular sums) + publish
        float z1 = (float)y1, z2 = (float)y2;
        float ea = 0, eb = 0;
#pragma unroll
        for (int c = 0; c < NSTEP; c++) {
            float zc1 = __shfl_sync(FULL, z1, c);
            float zc2 = __shfl_sync(FULL, z2, c);
            if (c <= lane) {
                float ss = (DTF * DTF) * (0.5f + (float)(lane - c));
                ea = fmaf(ss, zc1, ea);
                eb = fmaf(ss, zc2, eb);
            }
        }
        if (ls) {
            g_consts[NHID + lane]         = -ea;
            g_consts[NHID + NSTEP + lane] = (float)(lane + 1) * dtf - eb;
        }
        if (lh) g_consts[lane] = q0;
        __threadfence();                       // release
        if (lane == 0) atomicExch(&g_flag, 1u);
    } else {
        // ---- All other warps: spin (release by flag, not kernel boundary) ----
        while (*(volatile unsigned*)&g_flag == 0u) __nanosleep(64);
    }
    __threadfence();                           // acquire

    // ---- Per-warp constant copy ----
#pragma unroll
    for (int k = 0; k < 3; k++) {
        int i = k * 32 + lane;
        if (i < NHID + 2 * NSTEP) scw[w][i] = g_consts[i];
    }
    __syncwarp();

    // ---- Dot (stride-25, conflict-free) ----
    float dp = 0.f;
#pragma unroll
    for (int i = 0; i < NHID; i++) dp = fmaf(sx[t * NHID + i], scw[w][i], dp);

    strip[t] = dp;
    strip[128 + t] = p;
    strip[256 + t] = v;
    __syncwarp();

    // ---- Warp-local coalesced float4 store ----
    float4* ob4 = (float4*)(out + (size_t)base * NSTEP);
#pragma unroll
    for (int k = 0; k < 5; k++) {
        int j4 = w * 160 + k * 32 + lane;
        int j = 4 * j4;
        int r = j / NSTEP;
        int c = j - r * NSTEP;
        float dpr = strip[r];
        float pr  = strip[128 + r];
        float vr  = strip[256 + r];
        float4 vv;
        vv.x = fmaf(vr, scw[w][NHID + NSTEP + c    ], fmaf(dpr, scw[w][NHID + c    ], pr));
        vv.y = fmaf(vr, scw[w][NHID + NSTEP + c + 1], fmaf(dpr, scw[w][NHID + c + 1], pr));
        vv.z = fmaf(vr, scw[w][NHID + NSTEP + c + 2], fmaf(dpr, scw[w][NHID + c + 2], pr));
        vv.w = fmaf(vr, scw[w][NHID + NSTEP + c + 3], fmaf(dpr, scw[w][NHID + c + 3], pr));
        ob4[j4] = vv;
    }

    // ---- Per-launch reset (deterministic; last block clears flag+counter) ----
    __syncthreads();
    if (t == 0) {
        unsigned d = atomicAdd(&g_done, 1u);
        if (d == gridDim.x - 1u) {
            g_done = 0u;
            __threadfence();
            *(volatile unsigned*)&g_flag = 0u;
        }
    }
}

extern "C" void kernel_launch(void* const* d_in, const int* in_sizes, int n_in,
                              void* d_out, int out_size) {
    const float* x  = (const float*)d_in[0];
    const float* gp = (const float*)d_in[1];
    const float* gv = (const float*)d_in[2];
    const float* Af = (const float*)d_in[3];
    const float* Lq = (const float*)d_in[4];
    float* out = (float*)d_out;

    const int nB = out_size / NSTEP;     // out is [B, NSTEP]
    fused_kernel<<<nB / 128, 128>>>(x, gp, gv, Af, Lq, out);
}